// round 10
// baseline (speedup 1.0000x reference)
#include <cuda_runtime.h>

// ---------------- dimensions ----------------
#define NB    64      // batch
#define C0    16      // input channels
#define LIN   4096
#define K1    30
#define C1    32      // fused conv1 output channels
#define L1    4067    // LIN - K1 + 1
#define L1P   4096    // padded row stride for y1
#define LP1   811     // after maxpool k=20 s=5 ceil
#define P1P   816
#define K2    10
#define C2    64
#define L2    802     // LP1 - K2 + 1
#define L2P   804
#define BIN0  300
#define BIN1  100
#define NG    256     // LSTM gates (4*64)
#define HID   64

typedef unsigned long long ull;

// ---------------- device scratch (no mallocs allowed) ----------------
__device__ ull   g_W1d[C0*K1*C1];       // conv1 weights duplicated (w,w) [c][k][o]
__device__ float g_B1[C1];
__device__ float g_W2t[C1*K2*C2];       // conv2 weights transposed [c][k][o]
__device__ float g_y1[(size_t)NB*C1*L1P];
__device__ float g_p1[(size_t)NB*C1*P1P];
__device__ float g_y2[(size_t)NB*C2*L2P];
__device__ float g_pool0[(size_t)NB*C2*BIN0];
__device__ float g_pool1[(size_t)NB*C2*BIN1];
__device__ float g_bo[2*NB];            // branch outputs

// ---------------- math helpers ----------------
__device__ __forceinline__ float tanh_ap(float x) {
    float y;
    asm("tanh.approx.f32 %0, %1;" : "=f"(y) : "f"(x));
    return y;
}
__device__ __forceinline__ float sig_ap(float x) {
    return 0.5f * tanh_ap(0.5f * x) + 0.5f;
}
__device__ __forceinline__ float leaky(float v) {
    return v > 0.f ? v : 0.01f * v;
}
// f32x2 packed math (FFMA2 — ptxas never emits this from C++)
__device__ __forceinline__ ull pack2(float x) {
    ull r;
    asm("mov.b64 %0, {%1, %1};" : "=l"(r) : "f"(x));
    return r;
}
__device__ __forceinline__ ull packab(float a, float b) {
    ull r;
    asm("mov.b64 %0, {%1, %2};" : "=l"(r) : "f"(a), "f"(b));
    return r;
}
__device__ __forceinline__ ull fma2(ull a, ull b, ull c) {
    ull d;
    asm("fma.rn.f32x2 %0, %1, %2, %3;" : "=l"(d) : "l"(a), "l"(b), "l"(c));
    return d;
}
__device__ __forceinline__ float2 unpack2(ull v) {
    float2 r;
    asm("mov.b64 {%0, %1}, %2;" : "=f"(r.x), "=f"(r.y) : "l"(v));
    return r;
}

// ---------------- prep: fold dw+pw convs into one 16->32 k=30 conv ----------------
// Weights stored as duplicated (w,w) ull pairs for batch-pair FFMA2.
__global__ void prep1_kernel(const float* __restrict__ w_dw, const float* __restrict__ b_dw,
                             const float* __restrict__ w_pw, const float* __restrict__ b_pw) {
    int c = blockIdx.x;        // 0..15
    int o = threadIdx.x;       // 0..31
    int k = threadIdx.y;       // 0..29
    float s = 0.f;
    #pragma unroll
    for (int j = 0; j < 16; j++)
        s += w_pw[o*256 + c*16 + j] * w_dw[(c*16 + j)*K1 + k];
    g_W1d[(c*K1 + k)*C1 + o] = pack2(s);
    if (c == 0 && k == 0) {
        float bs = b_pw[o];
        for (int m = 0; m < 256; m++) bs += w_pw[o*256 + m] * b_dw[m];
        g_B1[o] = bs;
    }
}

__global__ void prep2_kernel(const float* __restrict__ w_c2) {
    int idx = blockIdx.x * 256 + threadIdx.x;
    if (idx >= C1*K2*C2) return;
    int o = idx & 63;
    int ck = idx >> 6;
    int k = ck % K2;
    int c = ck / K2;
    g_W2t[idx] = w_c2[(o*C1 + c)*K2 + k];
}

// ---------------- conv1: batch-pair f32x2, 16->32 k=30, + leaky ----------------
// Lanes = two batch samples (2bp, 2bp+1). x stored in smem as (x_b0,x_b1) ull:
// inner loop has ZERO pack movs (pure LDS.128 + uniform LDG.64 + FFMA2).
// 256 threads: o = tid>>3 (0..31), l0 = (tid&7)*8, l-tile 64.
// k chunked 16+14 (both 16B-aligned) -> live window 24 ull -> 3 CTAs/SM.
__global__ void __launch_bounds__(256, 3) conv1_kernel(const float* __restrict__ X) {
    __shared__ __align__(16) ull xs[C0][96];    // 93 used (64 tile + 29 halo), 12 KB
    const int bp   = blockIdx.y;                // batch pair 0..31
    const int base = blockIdx.x * 64;
    const int tid  = threadIdx.x;
    const float* xb0 = X + (size_t)(2*bp) * (C0*LIN);
    const float* xb1 = xb0 + (size_t)C0*LIN;
    for (int i = tid; i < C0*93; i += 256) {
        int c = i / 93, l = i - c*93;
        int gl = base + l;
        float v0 = 0.f, v1 = 0.f;
        if (gl < LIN) {
            v0 = xb0[(size_t)c*LIN + gl];
            v1 = xb1[(size_t)c*LIN + gl];
        }
        xs[c][l] = packab(v0, v1);
    }
    __syncthreads();

    const int o  = tid >> 3;          // 0..31
    const int l0 = (tid & 7) << 3;    // 0..56
    ull acc[8];
    #pragma unroll
    for (int j = 0; j < 8; j++) acc[j] = 0ull;

    #pragma unroll 1
    for (int c = 0; c < C0; c++) {
        const ull* wp = &g_W1d[c*(K1*C1) + o];
        {   // chunk A: k in [0,16), window x[l0 .. l0+23] (24 ull, 12x LDS.128)
            ull xd[24];
            const ulonglong2* x2 = reinterpret_cast<const ulonglong2*>(&xs[c][l0]);
            #pragma unroll
            for (int j = 0; j < 12; j++) {
                ulonglong2 v = x2[j];
                xd[2*j] = v.x; xd[2*j+1] = v.y;
            }
            #pragma unroll
            for (int k = 0; k < 16; k++) {
                ull wv = wp[k*C1];
                #pragma unroll
                for (int j = 0; j < 8; j++)
                    acc[j] = fma2(wv, xd[k + j], acc[j]);
            }
        }
        {   // chunk B: k in [16,30), window x[l0+16 .. l0+36] (load 22 ull, 11x LDS.128)
            ull xd[22];
            const ulonglong2* x2 = reinterpret_cast<const ulonglong2*>(&xs[c][l0 + 16]);
            #pragma unroll
            for (int j = 0; j < 11; j++) {
                ulonglong2 v = x2[j];
                xd[2*j] = v.x; xd[2*j+1] = v.y;
            }
            #pragma unroll
            for (int k = 16; k < 30; k++) {
                ull wv = wp[k*C1];
                #pragma unroll
                for (int j = 0; j < 8; j++)
                    acc[j] = fma2(wv, xd[k - 16 + j], acc[j]);
            }
        }
    }

    float bo = g_B1[o];
    int lg = base + l0;
    float* y0  = &g_y1[((size_t)(2*bp)*C1 + o)*L1P + lg];
    float* y1r = y0 + (size_t)C1*L1P;   // next batch sample, same channel
    float r0[8], r1[8];
    #pragma unroll
    for (int j = 0; j < 8; j++) {
        float2 v = unpack2(acc[j]);
        r0[j] = leaky(v.x + bo);
        r1[j] = leaky(v.y + bo);
    }
    if (lg + 8 <= L1) {
        reinterpret_cast<float4*>(y0)[0]  = make_float4(r0[0], r0[1], r0[2], r0[3]);
        reinterpret_cast<float4*>(y0)[1]  = make_float4(r0[4], r0[5], r0[6], r0[7]);
        reinterpret_cast<float4*>(y1r)[0] = make_float4(r1[0], r1[1], r1[2], r1[3]);
        reinterpret_cast<float4*>(y1r)[1] = make_float4(r1[4], r1[5], r1[6], r1[7]);
    } else {
        #pragma unroll
        for (int j = 0; j < 8; j++) {
            if (lg + j < L1) { y0[j] = r0[j]; y1r[j] = r1[j]; }
        }
    }
}

// ---------------- maxpool k=20 s=5 ceil_mode, two-stage (R3-exact) ----------------
__global__ void __launch_bounds__(256) maxpool_kernel() {
    int row = blockIdx.x;             // b*C1 + o
    __shared__ float m5[814];
    const float* r = &g_y1[(size_t)row * L1P];
    for (int q = threadIdx.x; q < 814; q += 256) {
        int s = 5*q;
        int e = s + 5; if (e > L1) e = L1;
        float m = r[s];
        for (int l = s + 1; l < e; l++) m = fmaxf(m, r[l]);
        m5[q] = m;
    }
    __syncthreads();
    float* out = &g_p1[(size_t)row * P1P];
    for (int i = threadIdx.x; i < LP1; i += 256)
        out[i] = fmaxf(fmaxf(m5[i], m5[i+1]), fmaxf(m5[i+2], m5[i+3]));
}

// ---------------- conv2: 32->64 k=10, + leaky, f32x2 (R3-exact) ----------------
__global__ void __launch_bounds__(256, 2) conv2_kernel(const float* __restrict__ b_c2) {
    __shared__ __align__(16) float xs[C1][144];
    const int b = blockIdx.y;
    const int base = blockIdx.x * 128;
    const int tid = threadIdx.x;
    for (int i = tid; i < C1*144; i += 256) {
        int c = i / 144, l = i - c*144;
        int gl = base + l;
        xs[c][l] = (gl < LP1) ? g_p1[((size_t)b*C1 + c)*P1P + gl] : 0.f;
    }
    __syncthreads();

    const int op = tid >> 3;          // 0..31
    const int l0 = (tid & 7) << 4;    // 0..112
    ull acc[16];
    #pragma unroll
    for (int j = 0; j < 16; j++) acc[j] = 0ull;

    #pragma unroll 1
    for (int c = 0; c < C1; c++) {
        ull xd[28];
        const float4* xr = reinterpret_cast<const float4*>(&xs[c][l0]);
        #pragma unroll
        for (int j = 0; j < 7; j++) {
            float4 v = xr[j];
            xd[4*j]   = pack2(v.x);
            xd[4*j+1] = pack2(v.y);
            xd[4*j+2] = pack2(v.z);
            xd[4*j+3] = pack2(v.w);
        }
        const ull* wp = reinterpret_cast<const ull*>(&g_W2t[c*(K2*C2) + 2*op]);
        #pragma unroll
        for (int k = 0; k < K2; k++) {
            ull wv = wp[k*32];        // pair (W2t[c,k,2op], W2t[c,k,2op+1])
            #pragma unroll
            for (int j = 0; j < 16; j++)
                acc[j] = fma2(wv, xd[k + j], acc[j]);
        }
    }

    float b0 = b_c2[2*op], b1 = b_c2[2*op + 1];
    int lg = base + l0;
    float* y0 = &g_y2[((size_t)b*C2 + 2*op)*L2P + lg];
    float* y1r = y0 + L2P;
    #pragma unroll
    for (int j = 0; j < 16; j++) {
        if (lg + j < L2) {
            float2 v = unpack2(acc[j]);
            y0[j]  = leaky(v.x + b0);
            y1r[j] = leaky(v.y + b1);
        }
    }
}

// ---------------- adaptive pool bin=300 (k=204, s=2) via segment prefix/suffix max ----------------
__global__ void __launch_bounds__(128) pool0_kernel() {
    int c = blockIdx.x, b = blockIdx.y;
    __shared__ float row[L2];
    __shared__ float m[401], P[401], S[401];
    const float* src = &g_y2[((size_t)b*C2 + c)*L2P];
    for (int i = threadIdx.x; i < L2; i += 128) row[i] = src[i];
    __syncthreads();
    for (int j = threadIdx.x; j < 401; j += 128) m[j] = fmaxf(row[2*j], row[2*j + 1]);
    __syncthreads();
    if (threadIdx.x < 8) {
        int s = threadIdx.x & 3;
        int lo = s * 102;
        int hi = lo + 101; if (hi > 400) hi = 400;
        if (threadIdx.x < 4) {
            float v = m[lo]; P[lo] = v;
            for (int j = lo + 1; j <= hi; j++) { v = fmaxf(v, m[j]); P[j] = v; }
        } else {
            float v = m[hi]; S[hi] = v;
            for (int j = hi - 1; j >= lo; j--) { v = fmaxf(v, m[j]); S[j] = v; }
        }
    }
    __syncthreads();
    for (int i = threadIdx.x; i < BIN0; i += 128)
        g_pool0[((size_t)b*C2 + c)*BIN0 + i] = fmaxf(S[i], P[i + 101]);
}

// ---------------- adaptive pool bin=100 (k=10, s=8) ----------------
__global__ void pool1_kernel() {
    int idx = blockIdx.x * blockDim.x + threadIdx.x;
    if (idx >= NB*C2*BIN1) return;
    int i = idx % BIN1;
    int t = idx / BIN1;
    int c = t % C2;
    int b = t / C2;
    const float* r = &g_y2[((size_t)b*C2 + c)*L2P + 8*i];
    float mv = r[0];
    #pragma unroll
    for (int j = 1; j < 10; j++) mv = fmaxf(mv, r[j]);
    g_pool1[((size_t)b*C2 + c)*BIN1 + i] = mv;
}

// ---------------- fused branch: conv(64->4,k3,p1)+leaky -> LSTM -> linear ----------------
__global__ void __launch_bounds__(256) branch_lstm_kernel(
    const float* __restrict__ wsc0, const float* __restrict__ bsc0,
    const float* __restrict__ wih0, const float* __restrict__ bih0,
    const float* __restrict__ whh0, const float* __restrict__ bhh0,
    const float* __restrict__ wlin0, const float* __restrict__ blin0,
    const float* __restrict__ wsc1, const float* __restrict__ bsc1,
    const float* __restrict__ wih1, const float* __restrict__ bih1,
    const float* __restrict__ whh1, const float* __restrict__ bhh1,
    const float* __restrict__ wlin1, const float* __restrict__ blin1)
{
    int b  = blockIdx.x;
    int br = blockIdx.y;
    int bin = br ? BIN1 : BIN0;
    const float* pool = br ? g_pool1 : g_pool0;
    const float* wsc  = br ? wsc1 : wsc0;
    const float* bsc  = br ? bsc1 : bsc0;
    const float* wih  = br ? wih1 : wih0;
    const float* bih  = br ? bih1 : bih0;
    const float* whh  = br ? whh1 : whh0;
    const float* bhh  = br ? bhh1 : bhh0;
    const float* wlin = br ? wlin1 : wlin0;
    const float* blin = br ? blin1 : blin0;

    __shared__ __align__(16) float xc4[BIN0*4];   // [t][f]
    __shared__ __align__(16) float hsh[HID];
    __shared__ float gsh[NG];
    int tid = threadIdx.x;

    // ---- conv 64->4, k=3, p=1, leaky ----
    const float* pb = pool + (size_t)b * C2 * bin;
    int nvals = 4 * bin;
    for (int v = tid; v < nvals; v += 256) {
        int f = v / bin, t = v - f*bin;
        const float* wf = wsc + f * (C2*3);
        float acc = bsc[f];
        for (int c = 0; c < C2; c++) {
            const float* pc = pb + c*bin;
            float w0 = wf[c*3], w1 = wf[c*3+1], w2 = wf[c*3+2];
            float s = w1 * pc[t];
            if (t > 0)       s += w0 * pc[t-1];
            if (t + 1 < bin) s += w2 * pc[t+1];
            acc += s;
        }
        xc4[t*4 + f] = leaky(acc);
    }

    // ---- LSTM ----
    int g = tid;   // 0..255 = gate index
    ull wr[32];
    const ull* w2 = reinterpret_cast<const ull*>(whh + g*HID);
    #pragma unroll
    for (int j = 0; j < 32; j++) wr[j] = w2[j];
    float4 wi = reinterpret_cast<const float4*>(wih)[g];
    float bb = bih[g] + bhh[g];

    float cc = 0.f;
    if (g < HID) hsh[g] = 0.f;
    __syncthreads();

    for (int t = 0; t < bin; t++) {
        float4 x4 = reinterpret_cast<const float4*>(xc4)[t];
        const ull* h2 = reinterpret_cast<const ull*>(hsh);
        ull a0 = 0ull, a1 = 0ull, a2 = 0ull, a3 = 0ull;
        #pragma unroll
        for (int j = 0; j < 8; j++) {
            a0 = fma2(wr[4*j],   h2[4*j],   a0);
            a1 = fma2(wr[4*j+1], h2[4*j+1], a1);
            a2 = fma2(wr[4*j+2], h2[4*j+2], a2);
            a3 = fma2(wr[4*j+3], h2[4*j+3], a3);
        }
        float2 v0 = unpack2(a0), v1 = unpack2(a1), v2 = unpack2(a2), v3 = unpack2(a3);
        float acc = bb + wi.x*x4.x + wi.y*x4.y + wi.z*x4.z + wi.w*x4.w
                  + ((v0.x + v0.y) + (v1.x + v1.y))
                  + ((v2.x + v2.y) + (v3.x + v3.y));
        gsh[g] = acc;
        __syncthreads();
        if (g < HID) {
            float i_ = sig_ap(gsh[g]);
            float f_ = sig_ap(gsh[HID + g]);
            float z_ = tanh_ap(gsh[2*HID + g]);
            float o_ = sig_ap(gsh[3*HID + g]);
            cc = f_*cc + i_*z_;
            hsh[g] = o_ * tanh_ap(cc);
        }
        __syncthreads();
    }

    if (g == 0) {
        float s = blin[0];
        for (int j = 0; j < HID; j++) s += hsh[j] * wlin[j];
        g_bo[br*NB + b] = s;
    }
}

// ---------------- final head: sigmoid(Linear(2->1)) ----------------
__global__ void final_kernel(const float* __restrict__ wrul, const float* __restrict__ brul,
                             float* __restrict__ out) {
    int i = threadIdx.x;
    if (i >= NB) return;
    float y = wrul[0]*g_bo[i] + wrul[1]*g_bo[NB + i] + brul[0];
    out[i] = 1.f / (1.f + __expf(-y));
}

// ---------------- launch ----------------
// One prep2 pad keeps conv1_kernel at launch index 3 = the profiled launch.
extern "C" void kernel_launch(void* const* d_in, const int* in_sizes, int n_in,
                              void* d_out, int out_size) {
    const float* X     = (const float*)d_in[0];
    const float* w_dw  = (const float*)d_in[1];
    const float* b_dw  = (const float*)d_in[2];
    const float* w_pw  = (const float*)d_in[3];
    const float* b_pw  = (const float*)d_in[4];
    const float* w_c2  = (const float*)d_in[5];
    const float* b_c2  = (const float*)d_in[6];
    const float* w_sc0 = (const float*)d_in[7];
    const float* b_sc0 = (const float*)d_in[8];
    const float* w_ih0 = (const float*)d_in[9];
    const float* b_ih0 = (const float*)d_in[10];
    const float* w_hh0 = (const float*)d_in[11];
    const float* b_hh0 = (const float*)d_in[12];
    const float* w_lin0= (const float*)d_in[13];
    const float* b_lin0= (const float*)d_in[14];
    const float* w_sc1 = (const float*)d_in[15];
    const float* b_sc1 = (const float*)d_in[16];
    const float* w_ih1 = (const float*)d_in[17];
    const float* b_ih1 = (const float*)d_in[18];
    const float* w_hh1 = (const float*)d_in[19];
    const float* b_hh1 = (const float*)d_in[20];
    const float* w_lin1= (const float*)d_in[21];
    const float* b_lin1= (const float*)d_in[22];
    const float* w_rul = (const float*)d_in[23];
    const float* b_rul = (const float*)d_in[24];

    prep1_kernel<<<16, dim3(32, 30)>>>(w_dw, b_dw, w_pw, b_pw);        // idx 0
    prep2_kernel<<<(C1*K2*C2 + 255)/256, 256>>>(w_c2);                 // idx 1
    prep2_kernel<<<(C1*K2*C2 + 255)/256, 256>>>(w_c2);                 // idx 2 (pad)

    conv1_kernel<<<dim3(64, 32), 256>>>(X);                            // idx 3 <- ncu target
    maxpool_kernel<<<NB*C1, 256>>>();
    conv2_kernel<<<dim3(7, NB), 256>>>(b_c2);

    pool0_kernel<<<dim3(C2, NB), 128>>>();
    pool1_kernel<<<(NB*C2*BIN1 + 255)/256, 256>>>();

    branch_lstm_kernel<<<dim3(NB, 2), 256>>>(
        w_sc0, b_sc0, w_ih0, b_ih0, w_hh0, b_hh0, w_lin0, b_lin0,
        w_sc1, b_sc1, w_ih1, b_ih1, w_hh1, b_hh1, w_lin1, b_lin1);

    final_kernel<<<1, 64>>>(w_rul, b_rul, (float*)d_out);
}

// round 11
// speedup vs baseline: 1.3806x; 1.3806x over previous
#include <cuda_runtime.h>

// ---------------- dimensions ----------------
#define NB    64      // batch
#define C0    16      // input channels
#define LIN   4096
#define K1    30
#define C1    32      // fused conv1 output channels
#define L1    4067    // LIN - K1 + 1
#define L1P   4096    // padded row stride for y1
#define LP1   811     // after maxpool k=20 s=5 ceil
#define P1P   816
#define K2    10
#define C2    64
#define L2    802     // LP1 - K2 + 1
#define L2P   804
#define BIN0  300
#define BIN1  100
#define NG    256     // LSTM gates (4*64)
#define HID   64

typedef unsigned long long ull;

// ---------------- device scratch (no mallocs allowed) ----------------
__device__ float g_W1[C0*K1*C1];        // composite conv1 weights [c][k][o]
__device__ float g_B1[C1];
__device__ float g_W2t[C1*K2*C2];       // conv2 weights transposed [c][k][o]
__device__ float g_y1[(size_t)NB*C1*L1P];
__device__ float g_p1[(size_t)NB*C1*P1P];
__device__ float g_y2[(size_t)NB*C2*L2P];
__device__ float g_pool0[(size_t)NB*C2*BIN0];
__device__ float g_pool1[(size_t)NB*C2*BIN1];
__device__ float g_bo[2*NB];            // branch outputs

// ---------------- math helpers ----------------
__device__ __forceinline__ float tanh_ap(float x) {
    float y;
    asm("tanh.approx.f32 %0, %1;" : "=f"(y) : "f"(x));
    return y;
}
__device__ __forceinline__ float sig_ap(float x) {
    return 0.5f * tanh_ap(0.5f * x) + 0.5f;
}
__device__ __forceinline__ float leaky(float v) {
    return v > 0.f ? v : 0.01f * v;
}
// f32x2 packed math (FFMA2 — ptxas never emits this from C++)
__device__ __forceinline__ ull pack2(float x) {
    ull r;
    asm("mov.b64 %0, {%1, %1};" : "=l"(r) : "f"(x));
    return r;
}
__device__ __forceinline__ ull fma2(ull a, ull b, ull c) {
    ull d;
    asm("fma.rn.f32x2 %0, %1, %2, %3;" : "=l"(d) : "l"(a), "l"(b), "l"(c));
    return d;
}
__device__ __forceinline__ float2 unpack2(ull v) {
    float2 r;
    asm("mov.b64 {%0, %1}, %2;" : "=f"(r.x), "=f"(r.y) : "l"(v));
    return r;
}

// ---------------- combined prep: conv1 fold (dw+pw) AND conv2 transpose ----------------
// blocks 0..15: prep1 work (c = blockIdx). blocks 16..95: prep2 work.
__global__ void prep_kernel(const float* __restrict__ w_dw, const float* __restrict__ b_dw,
                            const float* __restrict__ w_pw, const float* __restrict__ b_pw,
                            const float* __restrict__ w_c2) {
    int blk = blockIdx.x;
    int tid = threadIdx.x;
    if (blk < 16) {
        int c = blk;               // input channel 0..15
        int o = tid & 31;          // out channel 0..31
        for (int k = tid >> 5; k < K1; k += 8) {
            float s = 0.f;
            #pragma unroll
            for (int j = 0; j < 16; j++)
                s += w_pw[o*256 + c*16 + j] * w_dw[(c*16 + j)*K1 + k];
            g_W1[(c*K1 + k)*C1 + o] = s;
        }
        if (c == 0 && tid < 32) {
            float bs = b_pw[tid];
            for (int m = 0; m < 256; m++) bs += w_pw[tid*256 + m] * b_dw[m];
            g_B1[tid] = bs;
        }
    } else {
        int idx = (blk - 16) * 256 + tid;
        if (idx < C1*K2*C2) {
            int o = idx & 63;
            int ck = idx >> 6;
            int k = ck % K2;
            int c = ck / K2;
            g_W2t[idx] = w_c2[(o*C1 + c)*K2 + k];
        }
    }
}

// ---------------- conv1: fused dw+pw, 16->32 k=30, + leaky, f32x2 (R3-exact) ----------------
__global__ void __launch_bounds__(256, 2) conv1_kernel(const float* __restrict__ X) {
    __shared__ __align__(16) float xs[C0][160];
    const int b = blockIdx.y;
    const int base = blockIdx.x * 128;
    const int tid = threadIdx.x;
    const float* xb = X + (size_t)b * (C0*LIN);
    for (int i = tid; i < C0*160; i += 256) {
        int c = i / 160, l = i - c*160;
        int gl = base + l;
        xs[c][l] = (gl < LIN) ? xb[(size_t)c*LIN + gl] : 0.f;
    }
    __syncthreads();

    const int op = tid >> 4;          // 0..15 -> channels {2op, 2op+1}
    const int l0 = (tid & 15) << 3;   // 0..120
    ull acc[8];
    #pragma unroll
    for (int j = 0; j < 8; j++) acc[j] = 0ull;

    #pragma unroll 1
    for (int c = 0; c < C0; c++) {
        // load 40 inputs, duplicate each into both f32x2 lanes
        ull xd[40];
        const float4* xr = reinterpret_cast<const float4*>(&xs[c][l0]);
        #pragma unroll
        for (int j = 0; j < 10; j++) {
            float4 v = xr[j];
            xd[4*j]   = pack2(v.x);
            xd[4*j+1] = pack2(v.y);
            xd[4*j+2] = pack2(v.z);
            xd[4*j+3] = pack2(v.w);
        }
        const ull* wp = reinterpret_cast<const ull*>(&g_W1[c*(K1*C1) + 2*op]);
        #pragma unroll
        for (int k = 0; k < K1; k++) {
            ull wv = wp[k*16];        // pair (W[c,k,2op], W[c,k,2op+1])
            #pragma unroll
            for (int j = 0; j < 8; j++)
                acc[j] = fma2(wv, xd[k + j], acc[j]);
        }
    }

    float b0 = g_B1[2*op], b1 = g_B1[2*op + 1];
    float* y0 = &g_y1[((size_t)b*C1 + 2*op)*L1P + base + l0];
    float* y1r = y0 + L1P;
    int lg = base + l0;
    #pragma unroll
    for (int j = 0; j < 8; j++) {
        if (lg + j < L1) {
            float2 v = unpack2(acc[j]);
            y0[j]  = leaky(v.x + b0);
            y1r[j] = leaky(v.y + b1);
        }
    }
}

// ---------------- maxpool k=20 s=5 ceil_mode, two-stage (R3-exact) ----------------
__global__ void __launch_bounds__(256) maxpool_kernel() {
    int row = blockIdx.x;             // b*C1 + o
    __shared__ float m5[814];
    const float* r = &g_y1[(size_t)row * L1P];
    for (int q = threadIdx.x; q < 814; q += 256) {
        int s = 5*q;
        int e = s + 5; if (e > L1) e = L1;
        float m = r[s];
        for (int l = s + 1; l < e; l++) m = fmaxf(m, r[l]);
        m5[q] = m;
    }
    __syncthreads();
    float* out = &g_p1[(size_t)row * P1P];
    for (int i = threadIdx.x; i < LP1; i += 256)
        out[i] = fmaxf(fmaxf(m5[i], m5[i+1]), fmaxf(m5[i+2], m5[i+3]));
}

// ---------------- conv2: 32->64 k=10, + leaky, f32x2 (R3-exact) ----------------
__global__ void __launch_bounds__(256, 2) conv2_kernel(const float* __restrict__ b_c2) {
    __shared__ __align__(16) float xs[C1][144];
    const int b = blockIdx.y;
    const int base = blockIdx.x * 128;
    const int tid = threadIdx.x;
    for (int i = tid; i < C1*144; i += 256) {
        int c = i / 144, l = i - c*144;
        int gl = base + l;
        xs[c][l] = (gl < LP1) ? g_p1[((size_t)b*C1 + c)*P1P + gl] : 0.f;
    }
    __syncthreads();

    const int op = tid >> 3;          // 0..31
    const int l0 = (tid & 7) << 4;    // 0..112
    ull acc[16];
    #pragma unroll
    for (int j = 0; j < 16; j++) acc[j] = 0ull;

    #pragma unroll 1
    for (int c = 0; c < C1; c++) {
        ull xd[28];
        const float4* xr = reinterpret_cast<const float4*>(&xs[c][l0]);
        #pragma unroll
        for (int j = 0; j < 7; j++) {
            float4 v = xr[j];
            xd[4*j]   = pack2(v.x);
            xd[4*j+1] = pack2(v.y);
            xd[4*j+2] = pack2(v.z);
            xd[4*j+3] = pack2(v.w);
        }
        const ull* wp = reinterpret_cast<const ull*>(&g_W2t[c*(K2*C2) + 2*op]);
        #pragma unroll
        for (int k = 0; k < K2; k++) {
            ull wv = wp[k*32];        // pair (W2t[c,k,2op], W2t[c,k,2op+1])
            #pragma unroll
            for (int j = 0; j < 16; j++)
                acc[j] = fma2(wv, xd[k + j], acc[j]);
        }
    }

    float b0 = b_c2[2*op], b1 = b_c2[2*op + 1];
    int lg = base + l0;
    float* y0 = &g_y2[((size_t)b*C2 + 2*op)*L2P + lg];
    float* y1r = y0 + L2P;
    #pragma unroll
    for (int j = 0; j < 16; j++) {
        if (lg + j < L2) {
            float2 v = unpack2(acc[j]);
            y0[j]  = leaky(v.x + b0);
            y1r[j] = leaky(v.y + b1);
        }
    }
}

// ---------------- adaptive pool bin=300 (k=204, s=2) via segment prefix/suffix max ----------------
__global__ void __launch_bounds__(128) pool0_kernel() {
    int c = blockIdx.x, b = blockIdx.y;
    __shared__ float row[L2];
    __shared__ float m[401], P[401], S[401];
    const float* src = &g_y2[((size_t)b*C2 + c)*L2P];
    for (int i = threadIdx.x; i < L2; i += 128) row[i] = src[i];
    __syncthreads();
    for (int j = threadIdx.x; j < 401; j += 128) m[j] = fmaxf(row[2*j], row[2*j + 1]);
    __syncthreads();
    if (threadIdx.x < 8) {
        int s = threadIdx.x & 3;
        int lo = s * 102;
        int hi = lo + 101; if (hi > 400) hi = 400;
        if (threadIdx.x < 4) {
            float v = m[lo]; P[lo] = v;
            for (int j = lo + 1; j <= hi; j++) { v = fmaxf(v, m[j]); P[j] = v; }
        } else {
            float v = m[hi]; S[hi] = v;
            for (int j = hi - 1; j >= lo; j--) { v = fmaxf(v, m[j]); S[j] = v; }
        }
    }
    __syncthreads();
    for (int i = threadIdx.x; i < BIN0; i += 128)
        g_pool0[((size_t)b*C2 + c)*BIN0 + i] = fmaxf(S[i], P[i + 101]);
}

// ---------------- adaptive pool bin=100 (k=10, s=8) ----------------
__global__ void pool1_kernel() {
    int idx = blockIdx.x * blockDim.x + threadIdx.x;
    if (idx >= NB*C2*BIN1) return;
    int i = idx % BIN1;
    int t = idx / BIN1;
    int c = t % C2;
    int b = t / C2;
    const float* r = &g_y2[((size_t)b*C2 + c)*L2P + 8*i];
    float mv = r[0];
    #pragma unroll
    for (int j = 1; j < 10; j++) mv = fmaxf(mv, r[j]);
    g_pool1[((size_t)b*C2 + c)*BIN1 + i] = mv;
}

// ---------------- fused branch: conv(64->4,k3,p1)+leaky -> LSTM -> linear ----------------
__global__ void __launch_bounds__(256) branch_lstm_kernel(
    const float* __restrict__ wsc0, const float* __restrict__ bsc0,
    const float* __restrict__ wih0, const float* __restrict__ bih0,
    const float* __restrict__ whh0, const float* __restrict__ bhh0,
    const float* __restrict__ wlin0, const float* __restrict__ blin0,
    const float* __restrict__ wsc1, const float* __restrict__ bsc1,
    const float* __restrict__ wih1, const float* __restrict__ bih1,
    const float* __restrict__ whh1, const float* __restrict__ bhh1,
    const float* __restrict__ wlin1, const float* __restrict__ blin1)
{
    int b  = blockIdx.x;
    int br = blockIdx.y;
    int bin = br ? BIN1 : BIN0;
    const float* pool = br ? g_pool1 : g_pool0;
    const float* wsc  = br ? wsc1 : wsc0;
    const float* bsc  = br ? bsc1 : bsc0;
    const float* wih  = br ? wih1 : wih0;
    const float* bih  = br ? bih1 : bih0;
    const float* whh  = br ? whh1 : whh0;
    const float* bhh  = br ? bhh1 : bhh0;
    const float* wlin = br ? wlin1 : wlin0;
    const float* blin = br ? blin1 : blin0;

    __shared__ __align__(16) float xc4[BIN0*4];   // [t][f]
    __shared__ __align__(16) float hsh[HID];
    __shared__ float gsh[NG];
    int tid = threadIdx.x;

    // ---- conv 64->4, k=3, p=1, leaky ----
    const float* pb = pool + (size_t)b * C2 * bin;
    int nvals = 4 * bin;
    for (int v = tid; v < nvals; v += 256) {
        int f = v / bin, t = v - f*bin;
        const float* wf = wsc + f * (C2*3);
        float acc = bsc[f];
        for (int c = 0; c < C2; c++) {
            const float* pc = pb + c*bin;
            float w0 = wf[c*3], w1 = wf[c*3+1], w2 = wf[c*3+2];
            float s = w1 * pc[t];
            if (t > 0)       s += w0 * pc[t-1];
            if (t + 1 < bin) s += w2 * pc[t+1];
            acc += s;
        }
        xc4[t*4 + f] = leaky(acc);
    }

    // ---- LSTM ----
    int g = tid;   // 0..255 = gate index
    ull wr[32];
    const ull* w2 = reinterpret_cast<const ull*>(whh + g*HID);
    #pragma unroll
    for (int j = 0; j < 32; j++) wr[j] = w2[j];
    float4 wi = reinterpret_cast<const float4*>(wih)[g];
    float bb = bih[g] + bhh[g];

    float cc = 0.f;
    if (g < HID) hsh[g] = 0.f;
    __syncthreads();

    for (int t = 0; t < bin; t++) {
        float4 x4 = reinterpret_cast<const float4*>(xc4)[t];
        const ull* h2 = reinterpret_cast<const ull*>(hsh);
        ull a0 = 0ull, a1 = 0ull, a2 = 0ull, a3 = 0ull;
        #pragma unroll
        for (int j = 0; j < 8; j++) {
            a0 = fma2(wr[4*j],   h2[4*j],   a0);
            a1 = fma2(wr[4*j+1], h2[4*j+1], a1);
            a2 = fma2(wr[4*j+2], h2[4*j+2], a2);
            a3 = fma2(wr[4*j+3], h2[4*j+3], a3);
        }
        float2 v0 = unpack2(a0), v1 = unpack2(a1), v2 = unpack2(a2), v3 = unpack2(a3);
        float acc = bb + wi.x*x4.x + wi.y*x4.y + wi.z*x4.z + wi.w*x4.w
                  + ((v0.x + v0.y) + (v1.x + v1.y))
                  + ((v2.x + v2.y) + (v3.x + v3.y));
        gsh[g] = acc;
        __syncthreads();
        if (g < HID) {
            float i_ = sig_ap(gsh[g]);
            float f_ = sig_ap(gsh[HID + g]);
            float z_ = tanh_ap(gsh[2*HID + g]);
            float o_ = sig_ap(gsh[3*HID + g]);
            cc = f_*cc + i_*z_;
            hsh[g] = o_ * tanh_ap(cc);
        }
        __syncthreads();
    }

    if (g == 0) {
        float s = blin[0];
        for (int j = 0; j < HID; j++) s += hsh[j] * wlin[j];
        g_bo[br*NB + b] = s;
    }
}

// ---------------- final head: sigmoid(Linear(2->1)) ----------------
__global__ void final_kernel(const float* __restrict__ wrul, const float* __restrict__ brul,
                             float* __restrict__ out) {
    int i = threadIdx.x;
    if (i >= NB) return;
    float y = wrul[0]*g_bo[i] + wrul[1]*g_bo[NB + i] + brul[0];
    out[i] = 1.f / (1.f + __expf(-y));
}

// ---------------- launch ----------------
// Order: prep(0), conv1(1), maxpool(2), conv2(3) <- profiled slot is index 3.
extern "C" void kernel_launch(void* const* d_in, const int* in_sizes, int n_in,
                              void* d_out, int out_size) {
    const float* X     = (const float*)d_in[0];
    const float* w_dw  = (const float*)d_in[1];
    const float* b_dw  = (const float*)d_in[2];
    const float* w_pw  = (const float*)d_in[3];
    const float* b_pw  = (const float*)d_in[4];
    const float* w_c2  = (const float*)d_in[5];
    const float* b_c2  = (const float*)d_in[6];
    const float* w_sc0 = (const float*)d_in[7];
    const float* b_sc0 = (const float*)d_in[8];
    const float* w_ih0 = (const float*)d_in[9];
    const float* b_ih0 = (const float*)d_in[10];
    const float* w_hh0 = (const float*)d_in[11];
    const float* b_hh0 = (const float*)d_in[12];
    const float* w_lin0= (const float*)d_in[13];
    const float* b_lin0= (const float*)d_in[14];
    const float* w_sc1 = (const float*)d_in[15];
    const float* b_sc1 = (const float*)d_in[16];
    const float* w_ih1 = (const float*)d_in[17];
    const float* b_ih1 = (const float*)d_in[18];
    const float* w_hh1 = (const float*)d_in[19];
    const float* b_hh1 = (const float*)d_in[20];
    const float* w_lin1= (const float*)d_in[21];
    const float* b_lin1= (const float*)d_in[22];
    const float* w_rul = (const float*)d_in[23];
    const float* b_rul = (const float*)d_in[24];

    prep_kernel<<<96, 256>>>(w_dw, b_dw, w_pw, b_pw, w_c2);            // idx 0

    conv1_kernel<<<dim3(32, NB), 256>>>(X);                            // idx 1
    maxpool_kernel<<<NB*C1, 256>>>();                                  // idx 2
    conv2_kernel<<<dim3(7, NB), 256>>>(b_c2);                          // idx 3 <- ncu target

    pool0_kernel<<<dim3(C2, NB), 128>>>();
    pool1_kernel<<<(NB*C2*BIN1 + 255)/256, 256>>>();

    branch_lstm_kernel<<<dim3(NB, 2), 256>>>(
        w_sc0, b_sc0, w_ih0, b_ih0, w_hh0, b_hh0, w_lin0, b_lin0,
        w_sc1, b_sc1, w_ih1, b_ih1, w_hh1, b_hh1, w_lin1, b_lin1);

    final_kernel<<<1, 64>>>(w_rul, b_rul, (float*)d_out);
}

// round 12
// speedup vs baseline: 1.4674x; 1.0629x over previous
#include <cuda_runtime.h>

// ---------------- dimensions ----------------
#define NB    64      // batch
#define C0    16      // input channels
#define LIN   4096
#define K1    30
#define C1    32      // fused conv1 output channels
#define L1    4067    // LIN - K1 + 1
#define L1P   4096    // padded row stride for y1
#define LP1   811     // after maxpool k=20 s=5 ceil
#define P1P   816
#define K2    10
#define C2    64
#define L2    802     // LP1 - K2 + 1
#define L2P   804
#define BIN0  300
#define BIN1  100
#define NG    256     // LSTM gates (4*64)
#define HID   64

typedef unsigned long long ull;

// ---------------- device scratch (no mallocs allowed) ----------------
__device__ float g_W1[C0*K1*C1];        // composite conv1 weights [c][k][o]
__device__ float g_B1[C1];
__device__ float g_W2t[C1*K2*C2];       // conv2 weights transposed [c][k][o]
__device__ float g_y1[(size_t)NB*C1*L1P];
__device__ float g_p1[(size_t)NB*C1*P1P];
__device__ float g_y2[(size_t)NB*C2*L2P];
__device__ float g_pool0[(size_t)NB*C2*BIN0];
__device__ float g_pool1[(size_t)NB*C2*BIN1];
__device__ float g_bo[2*NB];            // branch outputs

// ---------------- math helpers ----------------
__device__ __forceinline__ float tanh_ap(float x) {
    float y;
    asm("tanh.approx.f32 %0, %1;" : "=f"(y) : "f"(x));
    return y;
}
__device__ __forceinline__ float sig_ap(float x) {
    return 0.5f * tanh_ap(0.5f * x) + 0.5f;
}
__device__ __forceinline__ float leaky(float v) {
    return v > 0.f ? v : 0.01f * v;
}
// f32x2 packed math (FFMA2 — ptxas never emits this from C++)
__device__ __forceinline__ ull pack2(float x) {
    ull r;
    asm("mov.b64 %0, {%1, %1};" : "=l"(r) : "f"(x));
    return r;
}
__device__ __forceinline__ ull fma2(ull a, ull b, ull c) {
    ull d;
    asm("fma.rn.f32x2 %0, %1, %2, %3;" : "=l"(d) : "l"(a), "l"(b), "l"(c));
    return d;
}
__device__ __forceinline__ float2 unpack2(ull v) {
    float2 r;
    asm("mov.b64 {%0, %1}, %2;" : "=f"(r.x), "=f"(r.y) : "l"(v));
    return r;
}

// ---------------- combined prep: conv1 fold (dw+pw) AND conv2 transpose ----------------
// blocks 0..15: prep1 work (c = blockIdx). blocks 16..95: prep2 work.
__global__ void prep_kernel(const float* __restrict__ w_dw, const float* __restrict__ b_dw,
                            const float* __restrict__ w_pw, const float* __restrict__ b_pw,
                            const float* __restrict__ w_c2) {
    int blk = blockIdx.x;
    int tid = threadIdx.x;
    if (blk < 16) {
        int c = blk;               // input channel 0..15
        int o = tid & 31;          // out channel 0..31
        for (int k = tid >> 5; k < K1; k += 8) {
            float s = 0.f;
            #pragma unroll
            for (int j = 0; j < 16; j++)
                s += w_pw[o*256 + c*16 + j] * w_dw[(c*16 + j)*K1 + k];
            g_W1[(c*K1 + k)*C1 + o] = s;
        }
        if (c == 0 && tid < 32) {
            float bs = b_pw[tid];
            for (int m = 0; m < 256; m++) bs += w_pw[tid*256 + m] * b_dw[m];
            g_B1[tid] = bs;
        }
    } else {
        int idx = (blk - 16) * 256 + tid;
        if (idx < C1*K2*C2) {
            int o = idx & 63;
            int ck = idx >> 6;
            int k = ck % K2;
            int c = ck / K2;
            g_W2t[idx] = w_c2[(o*C1 + c)*K2 + k];
        }
    }
}

// ---------------- conv1: fused dw+pw, 16->32 k=30, + leaky, f32x2 (R3-exact) ----------------
__global__ void __launch_bounds__(256, 2) conv1_kernel(const float* __restrict__ X) {
    __shared__ __align__(16) float xs[C0][160];
    const int b = blockIdx.y;
    const int base = blockIdx.x * 128;
    const int tid = threadIdx.x;
    const float* xb = X + (size_t)b * (C0*LIN);
    for (int i = tid; i < C0*160; i += 256) {
        int c = i / 160, l = i - c*160;
        int gl = base + l;
        xs[c][l] = (gl < LIN) ? xb[(size_t)c*LIN + gl] : 0.f;
    }
    __syncthreads();

    const int op = tid >> 4;          // 0..15 -> channels {2op, 2op+1}
    const int l0 = (tid & 15) << 3;   // 0..120
    ull acc[8];
    #pragma unroll
    for (int j = 0; j < 8; j++) acc[j] = 0ull;

    #pragma unroll 1
    for (int c = 0; c < C0; c++) {
        // load 40 inputs, duplicate each into both f32x2 lanes
        ull xd[40];
        const float4* xr = reinterpret_cast<const float4*>(&xs[c][l0]);
        #pragma unroll
        for (int j = 0; j < 10; j++) {
            float4 v = xr[j];
            xd[4*j]   = pack2(v.x);
            xd[4*j+1] = pack2(v.y);
            xd[4*j+2] = pack2(v.z);
            xd[4*j+3] = pack2(v.w);
        }
        const ull* wp = reinterpret_cast<const ull*>(&g_W1[c*(K1*C1) + 2*op]);
        #pragma unroll
        for (int k = 0; k < K1; k++) {
            ull wv = wp[k*16];        // pair (W[c,k,2op], W[c,k,2op+1])
            #pragma unroll
            for (int j = 0; j < 8; j++)
                acc[j] = fma2(wv, xd[k + j], acc[j]);
        }
    }

    float b0 = g_B1[2*op], b1 = g_B1[2*op + 1];
    float* y0 = &g_y1[((size_t)b*C1 + 2*op)*L1P + base + l0];
    float* y1r = y0 + L1P;
    int lg = base + l0;
    #pragma unroll
    for (int j = 0; j < 8; j++) {
        if (lg + j < L1) {
            float2 v = unpack2(acc[j]);
            y0[j]  = leaky(v.x + b0);
            y1r[j] = leaky(v.y + b1);
        }
    }
}

// ---------------- maxpool k=20 s=5 ceil_mode, two-stage (R3-exact) ----------------
__global__ void __launch_bounds__(256) maxpool_kernel() {
    int row = blockIdx.x;             // b*C1 + o
    __shared__ float m5[814];
    const float* r = &g_y1[(size_t)row * L1P];
    for (int q = threadIdx.x; q < 814; q += 256) {
        int s = 5*q;
        int e = s + 5; if (e > L1) e = L1;
        float m = r[s];
        for (int l = s + 1; l < e; l++) m = fmaxf(m, r[l]);
        m5[q] = m;
    }
    __syncthreads();
    float* out = &g_p1[(size_t)row * P1P];
    for (int i = threadIdx.x; i < LP1; i += 256)
        out[i] = fmaxf(fmaxf(m5[i], m5[i+1]), fmaxf(m5[i+2], m5[i+3]));
}

// ---------------- conv2: 32->64 k=10, + leaky, f32x2 ----------------
// ONLY change this round: launch_bounds (256,2) -> (256,3).
// ptxas already allocates 84 regs; 84*768 = 64512 <= 64K regfile, so the cap
// adds a third resident CTA (16 -> 24 warps/SM) with no spills expected.
__global__ void __launch_bounds__(256, 3) conv2_kernel(const float* __restrict__ b_c2) {
    __shared__ __align__(16) float xs[C1][144];
    const int b = blockIdx.y;
    const int base = blockIdx.x * 128;
    const int tid = threadIdx.x;
    for (int i = tid; i < C1*144; i += 256) {
        int c = i / 144, l = i - c*144;
        int gl = base + l;
        xs[c][l] = (gl < LP1) ? g_p1[((size_t)b*C1 + c)*P1P + gl] : 0.f;
    }
    __syncthreads();

    const int op = tid >> 3;          // 0..31
    const int l0 = (tid & 7) << 4;    // 0..112
    ull acc[16];
    #pragma unroll
    for (int j = 0; j < 16; j++) acc[j] = 0ull;

    #pragma unroll 1
    for (int c = 0; c < C1; c++) {
        ull xd[28];
        const float4* xr = reinterpret_cast<const float4*>(&xs[c][l0]);
        #pragma unroll
        for (int j = 0; j < 7; j++) {
            float4 v = xr[j];
            xd[4*j]   = pack2(v.x);
            xd[4*j+1] = pack2(v.y);
            xd[4*j+2] = pack2(v.z);
            xd[4*j+3] = pack2(v.w);
        }
        const ull* wp = reinterpret_cast<const ull*>(&g_W2t[c*(K2*C2) + 2*op]);
        #pragma unroll
        for (int k = 0; k < K2; k++) {
            ull wv = wp[k*32];        // pair (W2t[c,k,2op], W2t[c,k,2op+1])
            #pragma unroll
            for (int j = 0; j < 16; j++)
                acc[j] = fma2(wv, xd[k + j], acc[j]);
        }
    }

    float b0 = b_c2[2*op], b1 = b_c2[2*op + 1];
    int lg = base + l0;
    float* y0 = &g_y2[((size_t)b*C2 + 2*op)*L2P + lg];
    float* y1r = y0 + L2P;
    #pragma unroll
    for (int j = 0; j < 16; j++) {
        if (lg + j < L2) {
            float2 v = unpack2(acc[j]);
            y0[j]  = leaky(v.x + b0);
            y1r[j] = leaky(v.y + b1);
        }
    }
}

// ---------------- adaptive pool bin=300 (k=204, s=2) via segment prefix/suffix max ----------------
__global__ void __launch_bounds__(128) pool0_kernel() {
    int c = blockIdx.x, b = blockIdx.y;
    __shared__ float row[L2];
    __shared__ float m[401], P[401], S[401];
    const float* src = &g_y2[((size_t)b*C2 + c)*L2P];
    for (int i = threadIdx.x; i < L2; i += 128) row[i] = src[i];
    __syncthreads();
    for (int j = threadIdx.x; j < 401; j += 128) m[j] = fmaxf(row[2*j], row[2*j + 1]);
    __syncthreads();
    if (threadIdx.x < 8) {
        int s = threadIdx.x & 3;
        int lo = s * 102;
        int hi = lo + 101; if (hi > 400) hi = 400;
        if (threadIdx.x < 4) {
            float v = m[lo]; P[lo] = v;
            for (int j = lo + 1; j <= hi; j++) { v = fmaxf(v, m[j]); P[j] = v; }
        } else {
            float v = m[hi]; S[hi] = v;
            for (int j = hi - 1; j >= lo; j--) { v = fmaxf(v, m[j]); S[j] = v; }
        }
    }
    __syncthreads();
    for (int i = threadIdx.x; i < BIN0; i += 128)
        g_pool0[((size_t)b*C2 + c)*BIN0 + i] = fmaxf(S[i], P[i + 101]);
}

// ---------------- adaptive pool bin=100 (k=10, s=8) ----------------
__global__ void pool1_kernel() {
    int idx = blockIdx.x * blockDim.x + threadIdx.x;
    if (idx >= NB*C2*BIN1) return;
    int i = idx % BIN1;
    int t = idx / BIN1;
    int c = t % C2;
    int b = t / C2;
    const float* r = &g_y2[((size_t)b*C2 + c)*L2P + 8*i];
    float mv = r[0];
    #pragma unroll
    for (int j = 1; j < 10; j++) mv = fmaxf(mv, r[j]);
    g_pool1[((size_t)b*C2 + c)*BIN1 + i] = mv;
}

// ---------------- fused branch: conv(64->4,k3,p1)+leaky -> LSTM -> linear ----------------
__global__ void __launch_bounds__(256) branch_lstm_kernel(
    const float* __restrict__ wsc0, const float* __restrict__ bsc0,
    const float* __restrict__ wih0, const float* __restrict__ bih0,
    const float* __restrict__ whh0, const float* __restrict__ bhh0,
    const float* __restrict__ wlin0, const float* __restrict__ blin0,
    const float* __restrict__ wsc1, const float* __restrict__ bsc1,
    const float* __restrict__ wih1, const float* __restrict__ bih1,
    const float* __restrict__ whh1, const float* __restrict__ bhh1,
    const float* __restrict__ wlin1, const float* __restrict__ blin1)
{
    int b  = blockIdx.x;
    int br = blockIdx.y;
    int bin = br ? BIN1 : BIN0;
    const float* pool = br ? g_pool1 : g_pool0;
    const float* wsc  = br ? wsc1 : wsc0;
    const float* bsc  = br ? bsc1 : bsc0;
    const float* wih  = br ? wih1 : wih0;
    const float* bih  = br ? bih1 : bih0;
    const float* whh  = br ? whh1 : whh0;
    const float* bhh  = br ? bhh1 : bhh0;
    const float* wlin = br ? wlin1 : wlin0;
    const float* blin = br ? blin1 : blin0;

    __shared__ __align__(16) float xc4[BIN0*4];   // [t][f]
    __shared__ __align__(16) float hsh[HID];
    __shared__ float gsh[NG];
    int tid = threadIdx.x;

    // ---- conv 64->4, k=3, p=1, leaky ----
    const float* pb = pool + (size_t)b * C2 * bin;
    int nvals = 4 * bin;
    for (int v = tid; v < nvals; v += 256) {
        int f = v / bin, t = v - f*bin;
        const float* wf = wsc + f * (C2*3);
        float acc = bsc[f];
        for (int c = 0; c < C2; c++) {
            const float* pc = pb + c*bin;
            float w0 = wf[c*3], w1 = wf[c*3+1], w2 = wf[c*3+2];
            float s = w1 * pc[t];
            if (t > 0)       s += w0 * pc[t-1];
            if (t + 1 < bin) s += w2 * pc[t+1];
            acc += s;
        }
        xc4[t*4 + f] = leaky(acc);
    }

    // ---- LSTM ----
    int g = tid;   // 0..255 = gate index
    ull wr[32];
    const ull* w2 = reinterpret_cast<const ull*>(whh + g*HID);
    #pragma unroll
    for (int j = 0; j < 32; j++) wr[j] = w2[j];
    float4 wi = reinterpret_cast<const float4*>(wih)[g];
    float bb = bih[g] + bhh[g];

    float cc = 0.f;
    if (g < HID) hsh[g] = 0.f;
    __syncthreads();

    for (int t = 0; t < bin; t++) {
        float4 x4 = reinterpret_cast<const float4*>(xc4)[t];
        const ull* h2 = reinterpret_cast<const ull*>(hsh);
        ull a0 = 0ull, a1 = 0ull, a2 = 0ull, a3 = 0ull;
        #pragma unroll
        for (int j = 0; j < 8; j++) {
            a0 = fma2(wr[4*j],   h2[4*j],   a0);
            a1 = fma2(wr[4*j+1], h2[4*j+1], a1);
            a2 = fma2(wr[4*j+2], h2[4*j+2], a2);
            a3 = fma2(wr[4*j+3], h2[4*j+3], a3);
        }
        float2 v0 = unpack2(a0), v1 = unpack2(a1), v2 = unpack2(a2), v3 = unpack2(a3);
        float acc = bb + wi.x*x4.x + wi.y*x4.y + wi.z*x4.z + wi.w*x4.w
                  + ((v0.x + v0.y) + (v1.x + v1.y))
                  + ((v2.x + v2.y) + (v3.x + v3.y));
        gsh[g] = acc;
        __syncthreads();
        if (g < HID) {
            float i_ = sig_ap(gsh[g]);
            float f_ = sig_ap(gsh[HID + g]);
            float z_ = tanh_ap(gsh[2*HID + g]);
            float o_ = sig_ap(gsh[3*HID + g]);
            cc = f_*cc + i_*z_;
            hsh[g] = o_ * tanh_ap(cc);
        }
        __syncthreads();
    }

    if (g == 0) {
        float s = blin[0];
        for (int j = 0; j < HID; j++) s += hsh[j] * wlin[j];
        g_bo[br*NB + b] = s;
    }
}

// ---------------- final head: sigmoid(Linear(2->1)) ----------------
__global__ void final_kernel(const float* __restrict__ wrul, const float* __restrict__ brul,
                             float* __restrict__ out) {
    int i = threadIdx.x;
    if (i >= NB) return;
    float y = wrul[0]*g_bo[i] + wrul[1]*g_bo[NB + i] + brul[0];
    out[i] = 1.f / (1.f + __expf(-y));
}

// ---------------- launch ----------------
// Order: prep(0), conv1(1), maxpool(2), conv2(3) <- profiled slot is index 3.
extern "C" void kernel_launch(void* const* d_in, const int* in_sizes, int n_in,
                              void* d_out, int out_size) {
    const float* X     = (const float*)d_in[0];
    const float* w_dw  = (const float*)d_in[1];
    const float* b_dw  = (const float*)d_in[2];
    const float* w_pw  = (const float*)d_in[3];
    const float* b_pw  = (const float*)d_in[4];
    const float* w_c2  = (const float*)d_in[5];
    const float* b_c2  = (const float*)d_in[6];
    const float* w_sc0 = (const float*)d_in[7];
    const float* b_sc0 = (const float*)d_in[8];
    const float* w_ih0 = (const float*)d_in[9];
    const float* b_ih0 = (const float*)d_in[10];
    const float* w_hh0 = (const float*)d_in[11];
    const float* b_hh0 = (const float*)d_in[12];
    const float* w_lin0= (const float*)d_in[13];
    const float* b_lin0= (const float*)d_in[14];
    const float* w_sc1 = (const float*)d_in[15];
    const float* b_sc1 = (const float*)d_in[16];
    const float* w_ih1 = (const float*)d_in[17];
    const float* b_ih1 = (const float*)d_in[18];
    const float* w_hh1 = (const float*)d_in[19];
    const float* b_hh1 = (const float*)d_in[20];
    const float* w_lin1= (const float*)d_in[21];
    const float* b_lin1= (const float*)d_in[22];
    const float* w_rul = (const float*)d_in[23];
    const float* b_rul = (const float*)d_in[24];

    prep_kernel<<<96, 256>>>(w_dw, b_dw, w_pw, b_pw, w_c2);            // idx 0

    conv1_kernel<<<dim3(32, NB), 256>>>(X);                            // idx 1
    maxpool_kernel<<<NB*C1, 256>>>();                                  // idx 2
    conv2_kernel<<<dim3(7, NB), 256>>>(b_c2);                          // idx 3 <- ncu target

    pool0_kernel<<<dim3(C2, NB), 128>>>();
    pool1_kernel<<<(NB*C2*BIN1 + 255)/256, 256>>>();

    branch_lstm_kernel<<<dim3(NB, 2), 256>>>(
        w_sc0, b_sc0, w_ih0, b_ih0, w_hh0, b_hh0, w_lin0, b_lin0,
        w_sc1, b_sc1, w_ih1, b_ih1, w_hh1, b_hh1, w_lin1, b_lin1);

    final_kernel<<<1, 64>>>(w_rul, b_rul, (float*)d_out);
}

// round 13
// speedup vs baseline: 1.5074x; 1.0272x over previous
#include <cuda_runtime.h>

// ---------------- dimensions ----------------
#define NB    64      // batch
#define C0    16      // input channels
#define LIN   4096
#define K1    30
#define C1    32      // fused conv1 output channels
#define L1    4067    // LIN - K1 + 1
#define L1P   4096    // padded row stride for y1
#define LP1   811     // after maxpool k=20 s=5 ceil
#define P1P   816
#define K2    10
#define C2    64
#define L2    802     // LP1 - K2 + 1
#define L2P   804
#define BIN0  300
#define BIN1  100
#define NG    256     // LSTM gates (4*64)
#define HID   64

typedef unsigned long long ull;

// ---------------- device scratch (no mallocs allowed) ----------------
__device__ float g_W1[C0*K1*C1];        // composite conv1 weights [c][k][o]
__device__ float g_B1[C1];
__device__ float g_W2t[C1*K2*C2];       // conv2 weights transposed [c][k][o]
__device__ float g_y1[(size_t)NB*C1*L1P];
__device__ float g_p1[(size_t)NB*C1*P1P];
__device__ float g_y2[(size_t)NB*C2*L2P];
__device__ float g_pool0[(size_t)NB*C2*BIN0];
__device__ float g_pool1[(size_t)NB*C2*BIN1];
__device__ float g_bo[2*NB];            // branch outputs

// ---------------- math helpers ----------------
__device__ __forceinline__ float tanh_ap(float x) {
    float y;
    asm("tanh.approx.f32 %0, %1;" : "=f"(y) : "f"(x));
    return y;
}
__device__ __forceinline__ float sig_ap(float x) {
    return 0.5f * tanh_ap(0.5f * x) + 0.5f;
}
__device__ __forceinline__ float leaky(float v) {
    return v > 0.f ? v : 0.01f * v;
}
// f32x2 packed math (FFMA2 — ptxas never emits this from C++)
__device__ __forceinline__ ull pack2(float x) {
    ull r;
    asm("mov.b64 %0, {%1, %1};" : "=l"(r) : "f"(x));
    return r;
}
__device__ __forceinline__ ull fma2(ull a, ull b, ull c) {
    ull d;
    asm("fma.rn.f32x2 %0, %1, %2, %3;" : "=l"(d) : "l"(a), "l"(b), "l"(c));
    return d;
}
__device__ __forceinline__ float2 unpack2(ull v) {
    float2 r;
    asm("mov.b64 {%0, %1}, %2;" : "=f"(r.x), "=f"(r.y) : "l"(v));
    return r;
}

// ---------------- empty pad kernel (launch-index alignment for ncu) ----------------
__global__ void pad_kernel() {}

// ---------------- combined prep: conv1 fold (dw+pw) AND conv2 transpose ----------------
__global__ void prep_kernel(const float* __restrict__ w_dw, const float* __restrict__ b_dw,
                            const float* __restrict__ w_pw, const float* __restrict__ b_pw,
                            const float* __restrict__ w_c2) {
    int blk = blockIdx.x;
    int tid = threadIdx.x;
    if (blk < 16) {
        int c = blk;               // input channel 0..15
        int o = tid & 31;          // out channel 0..31
        for (int k = tid >> 5; k < K1; k += 8) {
            float s = 0.f;
            #pragma unroll
            for (int j = 0; j < 16; j++)
                s += w_pw[o*256 + c*16 + j] * w_dw[(c*16 + j)*K1 + k];
            g_W1[(c*K1 + k)*C1 + o] = s;
        }
        if (c == 0 && tid < 32) {
            float bs = b_pw[tid];
            for (int m = 0; m < 256; m++) bs += w_pw[tid*256 + m] * b_dw[m];
            g_B1[tid] = bs;
        }
    } else {
        int idx = (blk - 16) * 256 + tid;
        if (idx < C1*K2*C2) {
            int o = idx & 63;
            int ck = idx >> 6;
            int k = ck % K2;
            int c = ck / K2;
            g_W2t[idx] = w_c2[(o*C1 + c)*K2 + k];
        }
    }
}

// ---------------- conv1: fused dw+pw, 16->32 k=30, + leaky, f32x2 ----------------
// This round: k-chunked 16+14 (live window xd[24] = 48 regs) + launch_bounds(256,3).
// R12 established occupancy 2->3 as the win mechanism for these issue-starved kernels.
__global__ void __launch_bounds__(256, 3) conv1_kernel(const float* __restrict__ X) {
    __shared__ __align__(16) float xs[C0][160];
    const int b = blockIdx.y;
    const int base = blockIdx.x * 128;
    const int tid = threadIdx.x;
    const float* xb = X + (size_t)b * (C0*LIN);
    for (int i = tid; i < C0*160; i += 256) {
        int c = i / 160, l = i - c*160;
        int gl = base + l;
        xs[c][l] = (gl < LIN) ? xb[(size_t)c*LIN + gl] : 0.f;
    }
    __syncthreads();

    const int op = tid >> 4;          // 0..15 -> channels {2op, 2op+1}
    const int l0 = (tid & 15) << 3;   // 0..120
    ull acc[8];
    #pragma unroll
    for (int j = 0; j < 8; j++) acc[j] = 0ull;

    #pragma unroll 1
    for (int c = 0; c < C0; c++) {
        const float4* xr = reinterpret_cast<const float4*>(&xs[c][l0]);
        const ull* wp = reinterpret_cast<const ull*>(&g_W1[c*(K1*C1) + 2*op]);
        {   // chunk A: k in [0,16), window x[l0 .. l0+23]
            ull xd[24];
            #pragma unroll
            for (int j = 0; j < 6; j++) {
                float4 v = xr[j];
                xd[4*j]   = pack2(v.x);
                xd[4*j+1] = pack2(v.y);
                xd[4*j+2] = pack2(v.z);
                xd[4*j+3] = pack2(v.w);
            }
            #pragma unroll
            for (int k = 0; k < 16; k++) {
                ull wv = wp[k*16];
                #pragma unroll
                for (int j = 0; j < 8; j++)
                    acc[j] = fma2(wv, xd[k + j], acc[j]);
            }
        }
        {   // chunk B: k in [16,30), window x[l0+16 .. l0+36] (load 24, use 21)
            ull xd[24];
            #pragma unroll
            for (int j = 0; j < 6; j++) {
                float4 v = xr[4 + j];
                xd[4*j]   = pack2(v.x);
                xd[4*j+1] = pack2(v.y);
                xd[4*j+2] = pack2(v.z);
                xd[4*j+3] = pack2(v.w);
            }
            #pragma unroll
            for (int k = 16; k < 30; k++) {
                ull wv = wp[k*16];
                #pragma unroll
                for (int j = 0; j < 8; j++)
                    acc[j] = fma2(wv, xd[k - 16 + j], acc[j]);
            }
        }
    }

    float b0 = g_B1[2*op], b1 = g_B1[2*op + 1];
    float* y0 = &g_y1[((size_t)b*C1 + 2*op)*L1P + base + l0];
    float* y1r = y0 + L1P;
    int lg = base + l0;
    float r0[8], r1[8];
    #pragma unroll
    for (int j = 0; j < 8; j++) {
        float2 v = unpack2(acc[j]);
        r0[j] = leaky(v.x + b0);
        r1[j] = leaky(v.y + b1);
    }
    if (lg + 8 <= L1) {
        reinterpret_cast<float4*>(y0)[0]  = make_float4(r0[0], r0[1], r0[2], r0[3]);
        reinterpret_cast<float4*>(y0)[1]  = make_float4(r0[4], r0[5], r0[6], r0[7]);
        reinterpret_cast<float4*>(y1r)[0] = make_float4(r1[0], r1[1], r1[2], r1[3]);
        reinterpret_cast<float4*>(y1r)[1] = make_float4(r1[4], r1[5], r1[6], r1[7]);
    } else {
        #pragma unroll
        for (int j = 0; j < 8; j++) {
            if (lg + j < L1) { y0[j] = r0[j]; y1r[j] = r1[j]; }
        }
    }
}

// ---------------- maxpool k=20 s=5 ceil_mode, two-stage (R3-exact) ----------------
__global__ void __launch_bounds__(256) maxpool_kernel() {
    int row = blockIdx.x;             // b*C1 + o
    __shared__ float m5[814];
    const float* r = &g_y1[(size_t)row * L1P];
    for (int q = threadIdx.x; q < 814; q += 256) {
        int s = 5*q;
        int e = s + 5; if (e > L1) e = L1;
        float m = r[s];
        for (int l = s + 1; l < e; l++) m = fmaxf(m, r[l]);
        m5[q] = m;
    }
    __syncthreads();
    float* out = &g_p1[(size_t)row * P1P];
    for (int i = threadIdx.x; i < LP1; i += 256)
        out[i] = fmaxf(fmaxf(m5[i], m5[i+1]), fmaxf(m5[i+2], m5[i+3]));
}

// ---------------- conv2: 32->64 k=10, + leaky, f32x2 (R12-exact, occ 3) ----------------
__global__ void __launch_bounds__(256, 3) conv2_kernel(const float* __restrict__ b_c2) {
    __shared__ __align__(16) float xs[C1][144];
    const int b = blockIdx.y;
    const int base = blockIdx.x * 128;
    const int tid = threadIdx.x;
    for (int i = tid; i < C1*144; i += 256) {
        int c = i / 144, l = i - c*144;
        int gl = base + l;
        xs[c][l] = (gl < LP1) ? g_p1[((size_t)b*C1 + c)*P1P + gl] : 0.f;
    }
    __syncthreads();

    const int op = tid >> 3;          // 0..31
    const int l0 = (tid & 7) << 4;    // 0..112
    ull acc[16];
    #pragma unroll
    for (int j = 0; j < 16; j++) acc[j] = 0ull;

    #pragma unroll 1
    for (int c = 0; c < C1; c++) {
        ull xd[28];
        const float4* xr = reinterpret_cast<const float4*>(&xs[c][l0]);
        #pragma unroll
        for (int j = 0; j < 7; j++) {
            float4 v = xr[j];
            xd[4*j]   = pack2(v.x);
            xd[4*j+1] = pack2(v.y);
            xd[4*j+2] = pack2(v.z);
            xd[4*j+3] = pack2(v.w);
        }
        const ull* wp = reinterpret_cast<const ull*>(&g_W2t[c*(K2*C2) + 2*op]);
        #pragma unroll
        for (int k = 0; k < K2; k++) {
            ull wv = wp[k*32];        // pair (W2t[c,k,2op], W2t[c,k,2op+1])
            #pragma unroll
            for (int j = 0; j < 16; j++)
                acc[j] = fma2(wv, xd[k + j], acc[j]);
        }
    }

    float b0 = b_c2[2*op], b1 = b_c2[2*op + 1];
    int lg = base + l0;
    float* y0 = &g_y2[((size_t)b*C2 + 2*op)*L2P + lg];
    float* y1r = y0 + L2P;
    #pragma unroll
    for (int j = 0; j < 16; j++) {
        if (lg + j < L2) {
            float2 v = unpack2(acc[j]);
            y0[j]  = leaky(v.x + b0);
            y1r[j] = leaky(v.y + b1);
        }
    }
}

// ---------------- adaptive pool bin=300 (k=204, s=2) via segment prefix/suffix max ----------------
__global__ void __launch_bounds__(128) pool0_kernel() {
    int c = blockIdx.x, b = blockIdx.y;
    __shared__ float row[L2];
    __shared__ float m[401], P[401], S[401];
    const float* src = &g_y2[((size_t)b*C2 + c)*L2P];
    for (int i = threadIdx.x; i < L2; i += 128) row[i] = src[i];
    __syncthreads();
    for (int j = threadIdx.x; j < 401; j += 128) m[j] = fmaxf(row[2*j], row[2*j + 1]);
    __syncthreads();
    if (threadIdx.x < 8) {
        int s = threadIdx.x & 3;
        int lo = s * 102;
        int hi = lo + 101; if (hi > 400) hi = 400;
        if (threadIdx.x < 4) {
            float v = m[lo]; P[lo] = v;
            for (int j = lo + 1; j <= hi; j++) { v = fmaxf(v, m[j]); P[j] = v; }
        } else {
            float v = m[hi]; S[hi] = v;
            for (int j = hi - 1; j >= lo; j--) { v = fmaxf(v, m[j]); S[j] = v; }
        }
    }
    __syncthreads();
    for (int i = threadIdx.x; i < BIN0; i += 128)
        g_pool0[((size_t)b*C2 + c)*BIN0 + i] = fmaxf(S[i], P[i + 101]);
}

// ---------------- adaptive pool bin=100 (k=10, s=8) ----------------
__global__ void pool1_kernel() {
    int idx = blockIdx.x * blockDim.x + threadIdx.x;
    if (idx >= NB*C2*BIN1) return;
    int i = idx % BIN1;
    int t = idx / BIN1;
    int c = t % C2;
    int b = t / C2;
    const float* r = &g_y2[((size_t)b*C2 + c)*L2P + 8*i];
    float mv = r[0];
    #pragma unroll
    for (int j = 1; j < 10; j++) mv = fmaxf(mv, r[j]);
    g_pool1[((size_t)b*C2 + c)*BIN1 + i] = mv;
}

// ---------------- fused branch: conv(64->4,k3,p1)+leaky -> LSTM -> linear ----------------
__global__ void __launch_bounds__(256) branch_lstm_kernel(
    const float* __restrict__ wsc0, const float* __restrict__ bsc0,
    const float* __restrict__ wih0, const float* __restrict__ bih0,
    const float* __restrict__ whh0, const float* __restrict__ bhh0,
    const float* __restrict__ wlin0, const float* __restrict__ blin0,
    const float* __restrict__ wsc1, const float* __restrict__ bsc1,
    const float* __restrict__ wih1, const float* __restrict__ bih1,
    const float* __restrict__ whh1, const float* __restrict__ bhh1,
    const float* __restrict__ wlin1, const float* __restrict__ blin1)
{
    int b  = blockIdx.x;
    int br = blockIdx.y;
    int bin = br ? BIN1 : BIN0;
    const float* pool = br ? g_pool1 : g_pool0;
    const float* wsc  = br ? wsc1 : wsc0;
    const float* bsc  = br ? bsc1 : bsc0;
    const float* wih  = br ? wih1 : wih0;
    const float* bih  = br ? bih1 : bih0;
    const float* whh  = br ? whh1 : whh0;
    const float* bhh  = br ? bhh1 : bhh0;
    const float* wlin = br ? wlin1 : wlin0;
    const float* blin = br ? blin1 : blin0;

    __shared__ __align__(16) float xc4[BIN0*4];   // [t][f]
    __shared__ __align__(16) float hsh[HID];
    __shared__ float gsh[NG];
    int tid = threadIdx.x;

    // ---- conv 64->4, k=3, p=1, leaky ----
    const float* pb = pool + (size_t)b * C2 * bin;
    int nvals = 4 * bin;
    for (int v = tid; v < nvals; v += 256) {
        int f = v / bin, t = v - f*bin;
        const float* wf = wsc + f * (C2*3);
        float acc = bsc[f];
        for (int c = 0; c < C2; c++) {
            const float* pc = pb + c*bin;
            float w0 = wf[c*3], w1 = wf[c*3+1], w2 = wf[c*3+2];
            float s = w1 * pc[t];
            if (t > 0)       s += w0 * pc[t-1];
            if (t + 1 < bin) s += w2 * pc[t+1];
            acc += s;
        }
        xc4[t*4 + f] = leaky(acc);
    }

    // ---- LSTM ----
    int g = tid;   // 0..255 = gate index
    ull wr[32];
    const ull* w2 = reinterpret_cast<const ull*>(whh + g*HID);
    #pragma unroll
    for (int j = 0; j < 32; j++) wr[j] = w2[j];
    float4 wi = reinterpret_cast<const float4*>(wih)[g];
    float bb = bih[g] + bhh[g];

    float cc = 0.f;
    if (g < HID) hsh[g] = 0.f;
    __syncthreads();

    for (int t = 0; t < bin; t++) {
        float4 x4 = reinterpret_cast<const float4*>(xc4)[t];
        const ull* h2 = reinterpret_cast<const ull*>(hsh);
        ull a0 = 0ull, a1 = 0ull, a2 = 0ull, a3 = 0ull;
        #pragma unroll
        for (int j = 0; j < 8; j++) {
            a0 = fma2(wr[4*j],   h2[4*j],   a0);
            a1 = fma2(wr[4*j+1], h2[4*j+1], a1);
            a2 = fma2(wr[4*j+2], h2[4*j+2], a2);
            a3 = fma2(wr[4*j+3], h2[4*j+3], a3);
        }
        float2 v0 = unpack2(a0), v1 = unpack2(a1), v2 = unpack2(a2), v3 = unpack2(a3);
        float acc = bb + wi.x*x4.x + wi.y*x4.y + wi.z*x4.z + wi.w*x4.w
                  + ((v0.x + v0.y) + (v1.x + v1.y))
                  + ((v2.x + v2.y) + (v3.x + v3.y));
        gsh[g] = acc;
        __syncthreads();
        if (g < HID) {
            float i_ = sig_ap(gsh[g]);
            float f_ = sig_ap(gsh[HID + g]);
            float z_ = tanh_ap(gsh[2*HID + g]);
            float o_ = sig_ap(gsh[3*HID + g]);
            cc = f_*cc + i_*z_;
            hsh[g] = o_ * tanh_ap(cc);
        }
        __syncthreads();
    }

    if (g == 0) {
        float s = blin[0];
        for (int j = 0; j < HID; j++) s += hsh[j] * wlin[j];
        g_bo[br*NB + b] = s;
    }
}

// ---------------- final head: sigmoid(Linear(2->1)) ----------------
__global__ void final_kernel(const float* __restrict__ wrul, const float* __restrict__ brul,
                             float* __restrict__ out) {
    int i = threadIdx.x;
    if (i >= NB) return;
    float y = wrul[0]*g_bo[i] + wrul[1]*g_bo[NB + i] + brul[0];
    out[i] = 1.f / (1.f + __expf(-y));
}

// ---------------- launch ----------------
// Order: prep(0), pad(1), pad(2), conv1(3) <- profiled slot is index 3.
extern "C" void kernel_launch(void* const* d_in, const int* in_sizes, int n_in,
                              void* d_out, int out_size) {
    const float* X     = (const float*)d_in[0];
    const float* w_dw  = (const float*)d_in[1];
    const float* b_dw  = (const float*)d_in[2];
    const float* w_pw  = (const float*)d_in[3];
    const float* b_pw  = (const float*)d_in[4];
    const float* w_c2  = (const float*)d_in[5];
    const float* b_c2  = (const float*)d_in[6];
    const float* w_sc0 = (const float*)d_in[7];
    const float* b_sc0 = (const float*)d_in[8];
    const float* w_ih0 = (const float*)d_in[9];
    const float* b_ih0 = (const float*)d_in[10];
    const float* w_hh0 = (const float*)d_in[11];
    const float* b_hh0 = (const float*)d_in[12];
    const float* w_lin0= (const float*)d_in[13];
    const float* b_lin0= (const float*)d_in[14];
    const float* w_sc1 = (const float*)d_in[15];
    const float* b_sc1 = (const float*)d_in[16];
    const float* w_ih1 = (const float*)d_in[17];
    const float* b_ih1 = (const float*)d_in[18];
    const float* w_hh1 = (const float*)d_in[19];
    const float* b_hh1 = (const float*)d_in[20];
    const float* w_lin1= (const float*)d_in[21];
    const float* b_lin1= (const float*)d_in[22];
    const float* w_rul = (const float*)d_in[23];
    const float* b_rul = (const float*)d_in[24];

    prep_kernel<<<96, 256>>>(w_dw, b_dw, w_pw, b_pw, w_c2);            // idx 0
    pad_kernel<<<1, 32>>>();                                           // idx 1 (pad)
    pad_kernel<<<1, 32>>>();                                           // idx 2 (pad)

    conv1_kernel<<<dim3(32, NB), 256>>>(X);                            // idx 3 <- ncu target
    maxpool_kernel<<<NB*C1, 256>>>();
    conv2_kernel<<<dim3(7, NB), 256>>>(b_c2);

    pool0_kernel<<<dim3(C2, NB), 128>>>();
    pool1_kernel<<<(NB*C2*BIN1 + 255)/256, 256>>>();

    branch_lstm_kernel<<<dim3(NB, 2), 256>>>(
        w_sc0, b_sc0, w_ih0, b_ih0, w_hh0, b_hh0, w_lin0, b_lin0,
        w_sc1, b_sc1, w_ih1, b_ih1, w_hh1, b_hh1, w_lin1, b_lin1);

    final_kernel<<<1, 64>>>(w_rul, b_rul, (float*)d_out);
}

// round 17
// speedup vs baseline: 1.6487x; 1.0937x over previous
#include <cuda_runtime.h>

// ---------------- dimensions ----------------
#define NB    64      // batch
#define C0    16      // input channels
#define LIN   4096
#define K1    30
#define C1    32      // fused conv1 output channels
#define L1    4067    // LIN - K1 + 1
#define L1P   4096    // padded row stride for y1
#define LP1   811     // after maxpool k=20 s=5 ceil
#define P1P   816
#define K2    10
#define C2    64
#define L2    802     // LP1 - K2 + 1
#define L2P   804
#define BIN0  300
#define BIN1  100
#define NG    256     // LSTM gates (4*64)
#define HID   64

typedef unsigned long long ull;

// ---------------- device scratch (no mallocs allowed) ----------------
__device__ float g_W1[C0*K1*C1];        // composite conv1 weights [c][k][o]
__device__ float g_B1[C1];
__device__ float g_W2t[C1*K2*C2];       // conv2 weights transposed [c][k][o]
__device__ float g_y1[(size_t)NB*C1*L1P];
__device__ float g_p1[(size_t)NB*C1*P1P];
__device__ float g_y2[(size_t)NB*C2*L2P];
__device__ float g_pool0[(size_t)NB*C2*BIN0];
__device__ float g_pool1[(size_t)NB*C2*BIN1];
__device__ float g_bo[2*NB];            // branch outputs

// ---------------- math helpers ----------------
__device__ __forceinline__ float tanh_ap(float x) {
    float y;
    asm("tanh.approx.f32 %0, %1;" : "=f"(y) : "f"(x));
    return y;
}
__device__ __forceinline__ float sig_ap(float x) {
    return 0.5f * tanh_ap(0.5f * x) + 0.5f;
}
__device__ __forceinline__ float leaky(float v) {
    return v > 0.f ? v : 0.01f * v;
}
// f32x2 packed math (FFMA2 — ptxas never emits this from C++)
__device__ __forceinline__ ull pack2(float x) {
    ull r;
    asm("mov.b64 %0, {%1, %1};" : "=l"(r) : "f"(x));
    return r;
}
__device__ __forceinline__ ull fma2(ull a, ull b, ull c) {
    ull d;
    asm("fma.rn.f32x2 %0, %1, %2, %3;" : "=l"(d) : "l"(a), "l"(b), "l"(c));
    return d;
}
__device__ __forceinline__ float2 unpack2(ull v) {
    float2 r;
    asm("mov.b64 {%0, %1}, %2;" : "=f"(r.x), "=f"(r.y) : "l"(v));
    return r;
}

// ---------------- combined prep: conv1 fold (dw+pw) AND conv2 transpose ----------------
__global__ void prep_kernel(const float* __restrict__ w_dw, const float* __restrict__ b_dw,
                            const float* __restrict__ w_pw, const float* __restrict__ b_pw,
                            const float* __restrict__ w_c2) {
    int blk = blockIdx.x;
    int tid = threadIdx.x;
    if (blk < 16) {
        int c = blk;               // input channel 0..15
        int o = tid & 31;          // out channel 0..31
        for (int k = tid >> 5; k < K1; k += 8) {
            float s = 0.f;
            #pragma unroll
            for (int j = 0; j < 16; j++)
                s += w_pw[o*256 + c*16 + j] * w_dw[(c*16 + j)*K1 + k];
            g_W1[(c*K1 + k)*C1 + o] = s;
        }
        if (c == 0 && tid < 32) {
            float bs = b_pw[tid];
            for (int m = 0; m < 256; m++) bs += w_pw[tid*256 + m] * b_dw[m];
            g_B1[tid] = bs;
        }
    } else {
        int idx = (blk - 16) * 256 + tid;
        if (idx < C1*K2*C2) {
            int o = idx & 63;
            int ck = idx >> 6;
            int k = ck % K2;
            int c = ck / K2;
            g_W2t[idx] = w_c2[(o*C1 + c)*K2 + k];
        }
    }
}

// ---------------- conv1: fused dw+pw, 16->32 k=30, + leaky, f32x2 (R13-exact) ----------------
__global__ void __launch_bounds__(256, 3) conv1_kernel(const float* __restrict__ X) {
    __shared__ __align__(16) float xs[C0][160];
    const int b = blockIdx.y;
    const int base = blockIdx.x * 128;
    const int tid = threadIdx.x;
    const float* xb = X + (size_t)b * (C0*LIN);
    for (int i = tid; i < C0*160; i += 256) {
        int c = i / 160, l = i - c*160;
        int gl = base + l;
        xs[c][l] = (gl < LIN) ? xb[(size_t)c*LIN + gl] : 0.f;
    }
    __syncthreads();

    const int op = tid >> 4;          // 0..15 -> channels {2op, 2op+1}
    const int l0 = (tid & 15) << 3;   // 0..120
    ull acc[8];
    #pragma unroll
    for (int j = 0; j < 8; j++) acc[j] = 0ull;

    #pragma unroll 1
    for (int c = 0; c < C0; c++) {
        const float4* xr = reinterpret_cast<const float4*>(&xs[c][l0]);
        const ull* wp = reinterpret_cast<const ull*>(&g_W1[c*(K1*C1) + 2*op]);
        {   // chunk A: k in [0,16), window x[l0 .. l0+23]
            ull xd[24];
            #pragma unroll
            for (int j = 0; j < 6; j++) {
                float4 v = xr[j];
                xd[4*j]   = pack2(v.x);
                xd[4*j+1] = pack2(v.y);
                xd[4*j+2] = pack2(v.z);
                xd[4*j+3] = pack2(v.w);
            }
            #pragma unroll
            for (int k = 0; k < 16; k++) {
                ull wv = wp[k*16];
                #pragma unroll
                for (int j = 0; j < 8; j++)
                    acc[j] = fma2(wv, xd[k + j], acc[j]);
            }
        }
        {   // chunk B: k in [16,30), window x[l0+16 .. l0+36] (load 24, use 21)
            ull xd[24];
            #pragma unroll
            for (int j = 0; j < 6; j++) {
                float4 v = xr[4 + j];
                xd[4*j]   = pack2(v.x);
                xd[4*j+1] = pack2(v.y);
                xd[4*j+2] = pack2(v.z);
                xd[4*j+3] = pack2(v.w);
            }
            #pragma unroll
            for (int k = 16; k < 30; k++) {
                ull wv = wp[k*16];
                #pragma unroll
                for (int j = 0; j < 8; j++)
                    acc[j] = fma2(wv, xd[k - 16 + j], acc[j]);
            }
        }
    }

    float b0 = g_B1[2*op], b1 = g_B1[2*op + 1];
    float* y0 = &g_y1[((size_t)b*C1 + 2*op)*L1P + base + l0];
    float* y1r = y0 + L1P;
    int lg = base + l0;
    float r0[8], r1[8];
    #pragma unroll
    for (int j = 0; j < 8; j++) {
        float2 v = unpack2(acc[j]);
        r0[j] = leaky(v.x + b0);
        r1[j] = leaky(v.y + b1);
    }
    if (lg + 8 <= L1) {
        reinterpret_cast<float4*>(y0)[0]  = make_float4(r0[0], r0[1], r0[2], r0[3]);
        reinterpret_cast<float4*>(y0)[1]  = make_float4(r0[4], r0[5], r0[6], r0[7]);
        reinterpret_cast<float4*>(y1r)[0] = make_float4(r1[0], r1[1], r1[2], r1[3]);
        reinterpret_cast<float4*>(y1r)[1] = make_float4(r1[4], r1[5], r1[6], r1[7]);
    } else {
        #pragma unroll
        for (int j = 0; j < 8; j++) {
            if (lg + j < L1) { y0[j] = r0[j]; y1r[j] = r1[j]; }
        }
    }
}

// ---------------- maxpool k=20 s=5 ceil_mode, two-stage (R3-exact) ----------------
__global__ void __launch_bounds__(256) maxpool_kernel() {
    int row = blockIdx.x;             // b*C1 + o
    __shared__ float m5[814];
    const float* r = &g_y1[(size_t)row * L1P];
    for (int q = threadIdx.x; q < 814; q += 256) {
        int s = 5*q;
        int e = s + 5; if (e > L1) e = L1;
        float m = r[s];
        for (int l = s + 1; l < e; l++) m = fmaxf(m, r[l]);
        m5[q] = m;
    }
    __syncthreads();
    float* out = &g_p1[(size_t)row * P1P];
    for (int i = threadIdx.x; i < LP1; i += 256)
        out[i] = fmaxf(fmaxf(m5[i], m5[i+1]), fmaxf(m5[i+2], m5[i+3]));
}

// ---------------- conv2: 32->64 k=10, + leaky, f32x2 (R12-exact, occ 3) ----------------
__global__ void __launch_bounds__(256, 3) conv2_kernel(const float* __restrict__ b_c2) {
    __shared__ __align__(16) float xs[C1][144];
    const int b = blockIdx.y;
    const int base = blockIdx.x * 128;
    const int tid = threadIdx.x;
    for (int i = tid; i < C1*144; i += 256) {
        int c = i / 144, l = i - c*144;
        int gl = base + l;
        xs[c][l] = (gl < LP1) ? g_p1[((size_t)b*C1 + c)*P1P + gl] : 0.f;
    }
    __syncthreads();

    const int op = tid >> 3;          // 0..31
    const int l0 = (tid & 7) << 4;    // 0..112
    ull acc[16];
    #pragma unroll
    for (int j = 0; j < 16; j++) acc[j] = 0ull;

    #pragma unroll 1
    for (int c = 0; c < C1; c++) {
        ull xd[28];
        const float4* xr = reinterpret_cast<const float4*>(&xs[c][l0]);
        #pragma unroll
        for (int j = 0; j < 7; j++) {
            float4 v = xr[j];
            xd[4*j]   = pack2(v.x);
            xd[4*j+1] = pack2(v.y);
            xd[4*j+2] = pack2(v.z);
            xd[4*j+3] = pack2(v.w);
        }
        const ull* wp = reinterpret_cast<const ull*>(&g_W2t[c*(K2*C2) + 2*op]);
        #pragma unroll
        for (int k = 0; k < K2; k++) {
            ull wv = wp[k*32];        // pair (W2t[c,k,2op], W2t[c,k,2op+1])
            #pragma unroll
            for (int j = 0; j < 16; j++)
                acc[j] = fma2(wv, xd[k + j], acc[j]);
        }
    }

    float b0 = b_c2[2*op], b1 = b_c2[2*op + 1];
    int lg = base + l0;
    float* y0 = &g_y2[((size_t)b*C2 + 2*op)*L2P + lg];
    float* y1r = y0 + L2P;
    #pragma unroll
    for (int j = 0; j < 16; j++) {
        if (lg + j < L2) {
            float2 v = unpack2(acc[j]);
            y0[j]  = leaky(v.x + b0);
            y1r[j] = leaky(v.y + b1);
        }
    }
}

// ---------------- adaptive pool bin=300 (k=204, s=2) via segment prefix/suffix max ----------------
__global__ void __launch_bounds__(128) pool0_kernel() {
    int c = blockIdx.x, b = blockIdx.y;
    __shared__ float row[L2];
    __shared__ float m[401], P[401], S[401];
    const float* src = &g_y2[((size_t)b*C2 + c)*L2P];
    for (int i = threadIdx.x; i < L2; i += 128) row[i] = src[i];
    __syncthreads();
    for (int j = threadIdx.x; j < 401; j += 128) m[j] = fmaxf(row[2*j], row[2*j + 1]);
    __syncthreads();
    if (threadIdx.x < 8) {
        int s = threadIdx.x & 3;
        int lo = s * 102;
        int hi = lo + 101; if (hi > 400) hi = 400;
        if (threadIdx.x < 4) {
            float v = m[lo]; P[lo] = v;
            for (int j = lo + 1; j <= hi; j++) { v = fmaxf(v, m[j]); P[j] = v; }
        } else {
            float v = m[hi]; S[hi] = v;
            for (int j = hi - 1; j >= lo; j--) { v = fmaxf(v, m[j]); S[j] = v; }
        }
    }
    __syncthreads();
    for (int i = threadIdx.x; i < BIN0; i += 128)
        g_pool0[((size_t)b*C2 + c)*BIN0 + i] = fmaxf(S[i], P[i + 101]);
}

// ---------------- adaptive pool bin=100 (k=10, s=8) ----------------
__global__ void pool1_kernel() {
    int idx = blockIdx.x * blockDim.x + threadIdx.x;
    if (idx >= NB*C2*BIN1) return;
    int i = idx % BIN1;
    int t = idx / BIN1;
    int c = t % C2;
    int b = t / C2;
    const float* r = &g_y2[((size_t)b*C2 + c)*L2P + 8*i];
    float mv = r[0];
    #pragma unroll
    for (int j = 1; j < 10; j++) mv = fmaxf(mv, r[j]);
    g_pool1[((size_t)b*C2 + c)*BIN1 + i] = mv;
}

// ---------------- fused branch: conv(64->4,k3,p1)+leaky -> LSTM -> linear ----------------
// THIS ROUND: f-merged branch conv. Weights staged in smem as [(c,k) -> float4 over f];
// each thread owns time-step t, reads pc[t-1],pc[t],pc[t+1] ONCE per channel
// (coalesced across threads), updates 4 f-accumulators. 4x fewer global loads.
__global__ void __launch_bounds__(256) branch_lstm_kernel(
    const float* __restrict__ wsc0, const float* __restrict__ bsc0,
    const float* __restrict__ wih0, const float* __restrict__ bih0,
    const float* __restrict__ whh0, const float* __restrict__ bhh0,
    const float* __restrict__ wlin0, const float* __restrict__ blin0,
    const float* __restrict__ wsc1, const float* __restrict__ bsc1,
    const float* __restrict__ wih1, const float* __restrict__ bih1,
    const float* __restrict__ whh1, const float* __restrict__ bhh1,
    const float* __restrict__ wlin1, const float* __restrict__ blin1)
{
    int b  = blockIdx.x;
    int br = blockIdx.y;
    int bin = br ? BIN1 : BIN0;
    const float* pool = br ? g_pool1 : g_pool0;
    const float* wsc  = br ? wsc1 : wsc0;
    const float* bsc  = br ? bsc1 : bsc0;
    const float* wih  = br ? wih1 : wih0;
    const float* bih  = br ? bih1 : bih0;
    const float* whh  = br ? whh1 : whh0;
    const float* bhh  = br ? bhh1 : bhh0;
    const float* wlin = br ? wlin1 : wlin0;
    const float* blin = br ? blin1 : blin0;

    __shared__ __align__(16) float xc4[BIN0*4];   // [t][f]
    __shared__ __align__(16) float wsh[C2*3*4];   // [(c*3+k)*4 + f]
    __shared__ __align__(16) float hsh[HID];
    __shared__ float gsh[NG];
    int tid = threadIdx.x;

    // stage conv weights: wsc[f][c][k] -> wsh[(c*3+k)*4 + f]
    for (int i = tid; i < C2*3*4; i += 256) {
        int f = i / (C2*3);
        int ck = i - f*(C2*3);
        wsh[ck*4 + f] = wsc[i];
    }
    __syncthreads();

    // ---- conv 64->4, k=3, p=1, leaky (f-merged, coalesced) ----
    const float* pb = pool + (size_t)b * C2 * bin;
    float bs0 = bsc[0], bs1 = bsc[1], bs2 = bsc[2], bs3 = bsc[3];
    for (int t = tid; t < bin; t += 256) {
        float a0 = bs0, a1 = bs1, a2 = bs2, a3 = bs3;
        const float4* w4 = reinterpret_cast<const float4*>(wsh);
        #pragma unroll 4
        for (int c = 0; c < C2; c++) {
            const float* pc = pb + c*bin + t;
            float xm = (t > 0)       ? pc[-1] : 0.f;
            float x0 = pc[0];
            float xp = (t + 1 < bin) ? pc[1]  : 0.f;
            float4 w0 = w4[c*3 + 0];
            float4 w1 = w4[c*3 + 1];
            float4 w2 = w4[c*3 + 2];
            a0 += w0.x*xm + w1.x*x0 + w2.x*xp;
            a1 += w0.y*xm + w1.y*x0 + w2.y*xp;
            a2 += w0.z*xm + w1.z*x0 + w2.z*xp;
            a3 += w0.w*xm + w1.w*x0 + w2.w*xp;
        }
        reinterpret_cast<float4*>(xc4)[t] =
            make_float4(leaky(a0), leaky(a1), leaky(a2), leaky(a3));
    }

    // ---- LSTM ----
    int g = tid;   // 0..255 = gate index
    ull wr[32];
    const ull* w2 = reinterpret_cast<const ull*>(whh + g*HID);
    #pragma unroll
    for (int j = 0; j < 32; j++) wr[j] = w2[j];
    float4 wi = reinterpret_cast<const float4*>(wih)[g];
    float bb = bih[g] + bhh[g];

    float cc = 0.f;
    if (g < HID) hsh[g] = 0.f;
    __syncthreads();

    for (int t = 0; t < bin; t++) {
        float4 x4 = reinterpret_cast<const float4*>(xc4)[t];
        const ull* h2 = reinterpret_cast<const ull*>(hsh);
        ull a0 = 0ull, a1 = 0ull, a2 = 0ull, a3 = 0ull;
        #pragma unroll
        for (int j = 0; j < 8; j++) {
            a0 = fma2(wr[4*j],   h2[4*j],   a0);
            a1 = fma2(wr[4*j+1], h2[4*j+1], a1);
            a2 = fma2(wr[4*j+2], h2[4*j+2], a2);
            a3 = fma2(wr[4*j+3], h2[4*j+3], a3);
        }
        float2 v0 = unpack2(a0), v1 = unpack2(a1), v2 = unpack2(a2), v3 = unpack2(a3);
        float acc = bb + wi.x*x4.x + wi.y*x4.y + wi.z*x4.z + wi.w*x4.w
                  + ((v0.x + v0.y) + (v1.x + v1.y))
                  + ((v2.x + v2.y) + (v3.x + v3.y));
        gsh[g] = acc;
        __syncthreads();
        if (g < HID) {
            float i_ = sig_ap(gsh[g]);
            float f_ = sig_ap(gsh[HID + g]);
            float z_ = tanh_ap(gsh[2*HID + g]);
            float o_ = sig_ap(gsh[3*HID + g]);
            cc = f_*cc + i_*z_;
            hsh[g] = o_ * tanh_ap(cc);
        }
        __syncthreads();
    }

    if (g == 0) {
        float s = blin[0];
        for (int j = 0; j < HID; j++) s += hsh[j] * wlin[j];
        g_bo[br*NB + b] = s;
    }
}

// ---------------- final head: sigmoid(Linear(2->1)) ----------------
__global__ void final_kernel(const float* __restrict__ wrul, const float* __restrict__ brul,
                             float* __restrict__ out) {
    int i = threadIdx.x;
    if (i >= NB) return;
    float y = wrul[0]*g_bo[i] + wrul[1]*g_bo[NB + i] + brul[0];
    out[i] = 1.f / (1.f + __expf(-y));
}

// ---------------- launch ----------------
// Order: prep(0), conv1(1), maxpool(2), conv2(3) <- profiled slot (stability check).
extern "C" void kernel_launch(void* const* d_in, const int* in_sizes, int n_in,
                              void* d_out, int out_size) {
    const float* X     = (const float*)d_in[0];
    const float* w_dw  = (const float*)d_in[1];
    const float* b_dw  = (const float*)d_in[2];
    const float* w_pw  = (const float*)d_in[3];
    const float* b_pw  = (const float*)d_in[4];
    const float* w_c2  = (const float*)d_in[5];
    const float* b_c2  = (const float*)d_in[6];
    const float* w_sc0 = (const float*)d_in[7];
    const float* b_sc0 = (const float*)d_in[8];
    const float* w_ih0 = (const float*)d_in[9];
    const float* b_ih0 = (const float*)d_in[10];
    const float* w_hh0 = (const float*)d_in[11];
    const float* b_hh0 = (const float*)d_in[12];
    const float* w_lin0= (const float*)d_in[13];
    const float* b_lin0= (const float*)d_in[14];
    const float* w_sc1 = (const float*)d_in[15];
    const float* b_sc1 = (const float*)d_in[16];
    const float* w_ih1 = (const float*)d_in[17];
    const float* b_ih1 = (const float*)d_in[18];
    const float* w_hh1 = (const float*)d_in[19];
    const float* b_hh1 = (const float*)d_in[20];
    const float* w_lin1= (const float*)d_in[21];
    const float* b_lin1= (const float*)d_in[22];
    const float* w_rul = (const float*)d_in[23];
    const float* b_rul = (const float*)d_in[24];

    prep_kernel<<<96, 256>>>(w_dw, b_dw, w_pw, b_pw, w_c2);            // idx 0

    conv1_kernel<<<dim3(32, NB), 256>>>(X);                            // idx 1
    maxpool_kernel<<<NB*C1, 256>>>();                                  // idx 2
    conv2_kernel<<<dim3(7, NB), 256>>>(b_c2);                          // idx 3 <- ncu

    pool0_kernel<<<dim3(C2, NB), 128>>>();
    pool1_kernel<<<(NB*C2*BIN1 + 255)/256, 256>>>();

    branch_lstm_kernel<<<dim3(NB, 2), 256>>>(
        w_sc0, b_sc0, w_ih0, b_ih0, w_hh0, b_hh0, w_lin0, b_lin0,
        w_sc1, b_sc1, w_ih1, b_ih1, w_hh1, b_hh1, w_lin1, b_lin1);

    final_kernel<<<1, 64>>>(w_rul, b_rul, (float*)d_out);
}